// round 2
// baseline (speedup 1.0000x reference)
#include <cuda_runtime.h>
#include <cstdint>

// Problem constants
static const int Bb = 4, Ss = 4096, Dd = 1024, Hh = 16;

// Scratch (static device globals — allocation-free at kernel_launch time)
__device__ float g_qkv[16384 * 3072];        // 192 MB  [tokens, 3D]
__device__ float g_attn[256 * 1024 * 1024];  // 1 GB    score/prob scratch (max = global branch)
__device__ float g_ao[16384 * 1024];         // 64 MB   attention output [tokens, D]

// ---------------------------------------------------------------------------
// tf32 helpers
// ---------------------------------------------------------------------------
__device__ __forceinline__ uint32_t f2tf32(float f) {
    uint32_t u;
    asm("cvt.rna.tf32.f32 %0, %1;" : "=r"(u) : "f"(f));
    return u;
}

__device__ __forceinline__ void mma_tf32(float* c, const uint32_t* a, uint32_t b0, uint32_t b1) {
    asm("mma.sync.aligned.m16n8k8.row.col.f32.tf32.tf32.f32 "
        "{%0,%1,%2,%3}, {%4,%5,%6,%7}, {%8,%9}, {%0,%1,%2,%3};"
        : "+f"(c[0]), "+f"(c[1]), "+f"(c[2]), "+f"(c[3])
        : "r"(a[0]), "r"(a[1]), "r"(a[2]), "r"(a[3]), "r"(b0), "r"(b1));
}

// ---------------------------------------------------------------------------
// Generic batched tf32 GEMM:
//   C[m,n] = alpha * sum_k A[m,k] * Bmat(n,k)  (+ bias[n])
// B_NK = true : B stored [N][K] row-major (i.e. C = A @ B^T)   (ldb = row stride)
// B_NK = false: B stored [K][N] row-major (i.e. C = A @ B)
// Batch: blockIdx.z -> (win = z / Hb, h = z % Hb); pointer offsets win*ws + h*hs.
// All M, N multiples of BM/BN; K multiple of BK. No bounds checks needed.
// ---------------------------------------------------------------------------
template<int BM, int BN, int BK, int WSM, int WSN, bool B_NK>
__global__ void __launch_bounds__(256, 2)
gemm_tf32(const float* __restrict__ A, long long lda,
          const float* __restrict__ B, long long ldb,
          float* __restrict__ C, long long ldc,
          int K, float alpha, const float* __restrict__ bias,
          int Hb,
          long long wsA, long long hsA,
          long long wsB, long long hsB,
          long long wsC, long long hsC)
{
    constexpr int TM = BM / WSM;       // warp tile M
    constexpr int TN = BN / WSN;       // warp tile N
    constexpr int MT = TM / 16;        // mma tiles per warp (M)
    constexpr int NT = TN / 8;         // mma tiles per warp (N)
    constexpr int PAD = 4;
    constexpr int AS_COLS = BK + PAD;
    constexpr int BS_ROWS = B_NK ? BN : BK;
    constexpr int BS_COLS = (B_NK ? BK : BN) + PAD;

    __shared__ uint32_t As[BM * AS_COLS];
    __shared__ uint32_t Bs[BS_ROWS * BS_COLS];

    const int z = blockIdx.z;
    const int win = z / Hb;
    const int hh = z - win * Hb;
    A += win * wsA + hh * hsA;
    B += win * wsB + hh * hsB;
    C += win * wsC + hh * hsC;

    const long long m0 = (long long)blockIdx.y * BM;
    const long long n0 = (long long)blockIdx.x * BN;

    const int tid = threadIdx.x;
    const int lane = tid & 31;
    const int wid = tid >> 5;
    const int warpM = (wid % WSM) * TM;
    const int warpN = (wid / WSM) * TN;

    float acc[MT][NT][4] = {};

    for (int k0 = 0; k0 < K; k0 += BK) {
        // ---- stage A tile [BM][BK] (tf32-converted) ----
        #pragma unroll
        for (int i = 0; i < (BM * BK) / (256 * 4); ++i) {
            int lin = i * 256 + tid;
            int rr = lin / (BK / 4);
            int cc = (lin % (BK / 4)) * 4;
            float4 v = *reinterpret_cast<const float4*>(&A[(m0 + rr) * lda + (k0 + cc)]);
            uint32_t* d = &As[rr * AS_COLS + cc];
            d[0] = f2tf32(v.x); d[1] = f2tf32(v.y); d[2] = f2tf32(v.z); d[3] = f2tf32(v.w);
        }
        // ---- stage B tile ----
        if (B_NK) {
            #pragma unroll
            for (int i = 0; i < (BN * BK) / (256 * 4); ++i) {
                int lin = i * 256 + tid;
                int rr = lin / (BK / 4);            // n
                int cc = (lin % (BK / 4)) * 4;      // k
                float4 v = *reinterpret_cast<const float4*>(&B[(n0 + rr) * ldb + (k0 + cc)]);
                uint32_t* d = &Bs[rr * BS_COLS + cc];
                d[0] = f2tf32(v.x); d[1] = f2tf32(v.y); d[2] = f2tf32(v.z); d[3] = f2tf32(v.w);
            }
        } else {
            #pragma unroll
            for (int i = 0; i < (BK * BN) / (256 * 4); ++i) {
                int lin = i * 256 + tid;
                int rr = lin / (BN / 4);            // k
                int cc = (lin % (BN / 4)) * 4;      // n
                float4 v = *reinterpret_cast<const float4*>(&B[(k0 + rr) * ldb + (n0 + cc)]);
                uint32_t* d = &Bs[rr * BS_COLS + cc];
                d[0] = f2tf32(v.x); d[1] = f2tf32(v.y); d[2] = f2tf32(v.z); d[3] = f2tf32(v.w);
            }
        }
        __syncthreads();

        // ---- compute ----
        #pragma unroll
        for (int kk = 0; kk < BK; kk += 8) {
            uint32_t af[MT][4];
            const int kb = kk + (lane & 3);
            #pragma unroll
            for (int im = 0; im < MT; ++im) {
                int rbase = warpM + im * 16 + (lane >> 2);
                af[im][0] = As[rbase * AS_COLS + kb];
                af[im][1] = As[(rbase + 8) * AS_COLS + kb];
                af[im][2] = As[rbase * AS_COLS + kb + 4];
                af[im][3] = As[(rbase + 8) * AS_COLS + kb + 4];
            }
            #pragma unroll
            for (int in = 0; in < NT; ++in) {
                const int nn = warpN + in * 8 + (lane >> 2);
                uint32_t bf0, bf1;
                if (B_NK) {
                    bf0 = Bs[nn * BS_COLS + kb];
                    bf1 = Bs[nn * BS_COLS + kb + 4];
                } else {
                    bf0 = Bs[kb * BS_COLS + nn];
                    bf1 = Bs[(kb + 4) * BS_COLS + nn];
                }
                #pragma unroll
                for (int im = 0; im < MT; ++im)
                    mma_tf32(acc[im][in], af[im], bf0, bf1);
            }
        }
        __syncthreads();
    }

    // ---- epilogue ----
    #pragma unroll
    for (int im = 0; im < MT; ++im) {
        long long r0 = m0 + warpM + im * 16 + (lane >> 2);
        #pragma unroll
        for (int in = 0; in < NT; ++in) {
            long long c0 = n0 + warpN + in * 8 + 2 * (lane & 3);
            float b0v = bias ? bias[c0] : 0.0f;
            float b1v = bias ? bias[c0 + 1] : 0.0f;
            C[r0 * ldc + c0]           = alpha * acc[im][in][0] + b0v;
            C[r0 * ldc + c0 + 1]       = alpha * acc[im][in][1] + b1v;
            C[(r0 + 8) * ldc + c0]     = alpha * acc[im][in][2] + b0v;
            C[(r0 + 8) * ldc + c0 + 1] = alpha * acc[im][in][3] + b1v;
        }
    }
}

// ---------------------------------------------------------------------------
// Row softmax over S[row][0..W) with the faithful ADDITIVE +1.0 triu mask
// (col > row-within-window gets +1.0 added to the logit; NOT -inf masking).
// One block (128 threads) per row; row cached in smem (W <= 1024).
// ---------------------------------------------------------------------------
__global__ void softmax_mask_kernel(float* __restrict__ S, int W) {
    __shared__ float buf[1024];
    __shared__ float red[128];
    const long long row = blockIdx.x;
    const int r = (int)(row % W);
    float* p = S + row * (long long)W;
    const int tid = threadIdx.x;

    float lmax = -1e30f;
    for (int c = tid; c < W; c += 128) {
        float v = p[c] + (c > r ? 1.0f : 0.0f);
        buf[c] = v;
        lmax = fmaxf(lmax, v);
    }
    red[tid] = lmax;
    __syncthreads();
    for (int s = 64; s > 0; s >>= 1) {
        if (tid < s) red[tid] = fmaxf(red[tid], red[tid + s]);
        __syncthreads();
    }
    const float smax = red[0];
    __syncthreads();

    float lsum = 0.0f;
    for (int c = tid; c < W; c += 128) {
        float e = __expf(buf[c] - smax);
        buf[c] = e;
        lsum += e;
    }
    red[tid] = lsum;
    __syncthreads();
    for (int s = 64; s > 0; s >>= 1) {
        if (tid < s) red[tid] += red[tid + s];
        __syncthreads();
    }
    const float inv = 1.0f / red[0];
    for (int c = tid; c < W; c += 128) p[c] = buf[c] * inv;
}

// ---------------------------------------------------------------------------
// Host-side branch driver (all launches on default stream, graph-capturable)
// ---------------------------------------------------------------------------
static void run_branch(const float* x, const float* w_in, const float* b_in,
                       const float* w_out, const float* b_out,
                       int W, float* out,
                       float* qkv, float* attn, float* ao)
{
    const int M = Bb * Ss;          // 16384 tokens
    const int D3 = 3 * Dd;          // 3072
    const int nwin = (Bb * Ss) / W; // windows across batch
    const int npairs = nwin * Hh;   // (window, head) pairs
    const long long WD3 = (long long)W * D3;
    dim3 blk(256);

    // 1) QKV: qkv[M, 3D] = x @ w_in^T + b_in
    gemm_tf32<128, 128, 32, 4, 2, true><<<dim3(D3 / 128, M / 128, 1), blk>>>(
        x, Dd, w_in, Dd, qkv, D3, Dd, 1.0f, b_in,
        1, 0, 0, 0, 0, 0, 0);

    // 2) S = (Q K^T) / 8   per (window, head)
    gemm_tf32<128, 128, 32, 4, 2, true><<<dim3(W / 128, W / 128, npairs), blk>>>(
        qkv, D3, qkv + 1024, D3, attn, W, 64, 0.125f, nullptr,
        Hh, WD3, 64, WD3, 64, (long long)Hh * W * W, (long long)W * W);

    // 3) softmax with additive +1 triu mask
    softmax_mask_kernel<<<(unsigned)(npairs * W), 128>>>(attn, W);

    // 4) ao = P @ V   per (window, head)
    gemm_tf32<128, 64, 32, 8, 1, false><<<dim3(1, W / 128, npairs), blk>>>(
        attn, W, qkv + 2048, D3, ao, Dd, W, 1.0f, nullptr,
        Hh, (long long)Hh * W * W, (long long)W * W, WD3, 64, (long long)W * Dd, 64);

    // 5) out = ao @ w_out^T + b_out
    gemm_tf32<128, 128, 32, 4, 2, true><<<dim3(Dd / 128, M / 128, 1), blk>>>(
        ao, Dd, w_out, Dd, out, Dd, Dd, 1.0f, b_out,
        1, 0, 0, 0, 0, 0, 0);
}

extern "C" void kernel_launch(void* const* d_in, const int* in_sizes, int n_in,
                              void* d_out, int out_size)
{
    const float* lqs    = (const float*)d_in[0];
    const float* gqs    = (const float*)d_in[1];
    const float* wl_in  = (const float*)d_in[2];
    const float* bl_in  = (const float*)d_in[3];
    const float* wl_out = (const float*)d_in[4];
    const float* bl_out = (const float*)d_in[5];
    const float* wg_in  = (const float*)d_in[6];
    const float* bg_in  = (const float*)d_in[7];
    const float* wg_out = (const float*)d_in[8];
    const float* bg_out = (const float*)d_in[9];
    float* out = (float*)d_out;

    float *qkv, *attn, *ao;
    cudaGetSymbolAddress((void**)&qkv, g_qkv);
    cudaGetSymbolAddress((void**)&attn, g_attn);
    cudaGetSymbolAddress((void**)&ao, g_ao);

    // local branch (W=128) -> first 16M floats; global (W=1024) -> next 16M
    run_branch(lqs, wl_in, bl_in, wl_out, bl_out, 128, out, qkv, attn, ao);
    run_branch(gqs, wg_in, bg_in, wg_out, bg_out, 1024,
               out + (size_t)Bb * Ss * Dd, qkv, attn, ao);
}

// round 3
// speedup vs baseline: 1.5750x; 1.5750x over previous
#include <cuda_runtime.h>
#include <cstdint>

#define DEVINL __device__ __forceinline__

// Problem constants
static const int Bb = 4, Ss = 4096, Dd = 1024, Hh = 16;

// Scratch (static device globals — allocation-free)
__device__ __align__(128) float g_qkv[16384 * 3072];  // 192 MB [tokens, 3D]
__device__ __align__(128) float g_ao[16384 * 1024];   // 64 MB  [tokens, D]

// ---------------------------------------------------------------------------
// helpers
// ---------------------------------------------------------------------------
DEVINL uint32_t f2tf32(float f) {
    uint32_t u;
    asm("cvt.rna.tf32.f32 %0, %1;" : "=r"(u) : "f"(f));
    return u;
}
DEVINL void mma_tf32(float* c, const uint32_t* a, uint32_t b0, uint32_t b1) {
    asm("mma.sync.aligned.m16n8k8.row.col.f32.tf32.tf32.f32 "
        "{%0,%1,%2,%3}, {%4,%5,%6,%7}, {%8,%9}, {%0,%1,%2,%3};"
        : "+f"(c[0]), "+f"(c[1]), "+f"(c[2]), "+f"(c[3])
        : "r"(a[0]), "r"(a[1]), "r"(a[2]), "r"(a[3]), "r"(b0), "r"(b1));
}
DEVINL uint32_t smem_u32(const void* p) { return (uint32_t)__cvta_generic_to_shared(p); }
DEVINL void cp16(uint32_t dst, const void* src) {
    asm volatile("cp.async.ca.shared.global [%0], [%1], 16;" :: "r"(dst), "l"(src));
}
DEVINL void cp_commit() { asm volatile("cp.async.commit_group;"); }
template<int N> DEVINL void cp_wait() { asm volatile("cp.async.wait_group %0;" :: "n"(N)); }

// ---------------------------------------------------------------------------
// Projection GEMM: C[M,N] = A[M,K] @ W[N,K]^T + bias[N]
// BM=256, BN=128, BK=32. 8 warps, warp tile 64x64 (MT=4, NT=8).
// cp.async double-buffered smem (raw fp32), cvt.rna.tf32 at fragment load.
// ---------------------------------------------------------------------------
__global__ void __launch_bounds__(256, 1)
gemm_proj(const float* __restrict__ A, int lda,
          const float* __restrict__ W, int ldw,
          float* __restrict__ C, int ldc,
          int K, const float* __restrict__ bias)
{
    constexpr int BM = 256, BN = 128, BK = 32, LDS_ = 36;
    extern __shared__ float sm[];
    float* As = sm;                    // [2][BM][36]
    float* Bs = sm + 2 * BM * LDS_;    // [2][BN][36]

    const int tid = threadIdx.x, lane = tid & 31, wid = tid >> 5;
    const int warpM = (wid & 3) * 64, warpN = (wid >> 2) * 64;
    const long long m0 = (long long)blockIdx.y * BM;
    const long long n0 = (long long)blockIdx.x * BN;

    float acc[4][8][4] = {};

    auto issue = [&](int it, int buf) {
        long long k0 = (long long)it * BK;
        float* ad = As + buf * BM * LDS_;
        #pragma unroll
        for (int i = 0; i < 8; ++i) {
            int lin = i * 256 + tid;
            int r = lin >> 3, c4 = (lin & 7) * 4;
            cp16(smem_u32(ad + r * LDS_ + c4), A + (m0 + r) * lda + k0 + c4);
        }
        float* bd = Bs + buf * BN * LDS_;
        #pragma unroll
        for (int i = 0; i < 4; ++i) {
            int lin = i * 256 + tid;
            int r = lin >> 3, c4 = (lin & 7) * 4;
            cp16(smem_u32(bd + r * LDS_ + c4), W + (n0 + r) * ldw + k0 + c4);
        }
        cp_commit();
    };

    const int NIT = K / BK;
    issue(0, 0);
    int buf = 0;
    for (int it = 0; it < NIT; ++it) {
        cp_wait<0>();
        __syncthreads();                       // stage `it` visible; prev compute done
        if (it + 1 < NIT) issue(it + 1, buf ^ 1);

        const float* a = As + buf * BM * LDS_;
        const float* b = Bs + buf * BN * LDS_;
        #pragma unroll
        for (int kk = 0; kk < BK; kk += 8) {
            const int kb = kk + (lane & 3);
            uint32_t af[4][4];
            #pragma unroll
            for (int im = 0; im < 4; ++im) {
                int r = warpM + im * 16 + (lane >> 2);
                af[im][0] = f2tf32(a[r * LDS_ + kb]);
                af[im][1] = f2tf32(a[(r + 8) * LDS_ + kb]);
                af[im][2] = f2tf32(a[r * LDS_ + kb + 4]);
                af[im][3] = f2tf32(a[(r + 8) * LDS_ + kb + 4]);
            }
            #pragma unroll
            for (int in = 0; in < 8; ++in) {
                int nn = warpN + in * 8 + (lane >> 2);
                uint32_t b0 = f2tf32(b[nn * LDS_ + kb]);
                uint32_t b1 = f2tf32(b[nn * LDS_ + kb + 4]);
                #pragma unroll
                for (int im = 0; im < 4; ++im)
                    mma_tf32(acc[im][in], af[im], b0, b1);
            }
        }
        buf ^= 1;
    }

    #pragma unroll
    for (int im = 0; im < 4; ++im) {
        long long r = m0 + warpM + im * 16 + (lane >> 2);
        #pragma unroll
        for (int in = 0; in < 8; ++in) {
            long long c = n0 + warpN + in * 8 + 2 * (lane & 3);
            float b0 = bias[c], b1 = bias[c + 1];
            *(float2*)&C[r * ldc + c]       = make_float2(acc[im][in][0] + b0, acc[im][in][1] + b1);
            *(float2*)&C[(r + 8) * ldc + c] = make_float2(acc[im][in][2] + b0, acc[im][in][3] + b1);
        }
    }
}

// ---------------------------------------------------------------------------
// Fused attention: per (window, head), Q-tile of 128 rows, online softmax
// over key chunks of 128. S in regs; P via smem; additive +1.0 triu mask.
// 8 warps; warp owns 16 Q-rows x full width (row reductions stay in-warp).
// smem floats: sQ[128][68] @0, sK[128][68] @8704, sV[128][72] @17408,
//              sP[128][132] @26624  -> total 43520 f = 174080 B
// ---------------------------------------------------------------------------
__global__ void __launch_bounds__(256, 1)
attn_fused(const float* __restrict__ qkv, float* __restrict__ ao, int W, int nc)
{
    extern __shared__ float sm[];
    float* sQ = sm;
    float* sK = sm + 8704;
    float* sV = sm + 17408;
    float* sP = sm + 26624;

    const int tid = threadIdx.x, lane = tid & 31, wid = tid >> 5;
    const int pair = blockIdx.y;            // win*16 + h
    const int win = pair >> 4, h = pair & 15;
    const int q0 = blockIdx.x * 128;
    const long long base = (long long)win * W * 3072 + h * 64;
    const float* Qg = qkv + base + (long long)q0 * 3072;
    const float* Kg = qkv + base + 1024;
    const float* Vg = qkv + base + 2048;

    // stage Q (raw fp32; converted at fragment load)
    #pragma unroll
    for (int i = 0; i < 8; ++i) {
        int lin = i * 256 + tid;
        int r = lin >> 4, c4 = (lin & 15) * 4;
        cp16(smem_u32(sQ + r * 68 + c4), Qg + (long long)r * 3072 + c4);
    }
    cp_commit();

    float oacc[8][4] = {};
    float m_[2] = {-1e30f, -1e30f}, l_[2] = {0.f, 0.f};
    const int rw0 = q0 + wid * 16 + (lane >> 2);   // window-relative row (half 0)

    for (int c = 0; c < nc; ++c) {
        const float* Kc = Kg + (long long)c * 128 * 3072;
        const float* Vc = Vg + (long long)c * 128 * 3072;
        #pragma unroll
        for (int i = 0; i < 8; ++i) {
            int lin = i * 256 + tid;
            int r = lin >> 4, c4 = (lin & 15) * 4;
            cp16(smem_u32(sK + r * 68 + c4), Kc + (long long)r * 3072 + c4);
        }
        #pragma unroll
        for (int i = 0; i < 8; ++i) {
            int lin = i * 256 + tid;
            int r = lin >> 4, c4 = (lin & 15) * 4;
            cp16(smem_u32(sV + r * 72 + c4), Vc + (long long)r * 3072 + c4);
        }
        cp_commit();
        cp_wait<0>();
        __syncthreads();

        // ---- S = Q K^T (S tile rows: warp-private 16 rows x 128 cols) ----
        float sacc[16][4];
        #pragma unroll
        for (int i = 0; i < 16; ++i)
            sacc[i][0] = sacc[i][1] = sacc[i][2] = sacc[i][3] = 0.f;

        #pragma unroll
        for (int kk = 0; kk < 64; kk += 8) {
            const int kb = kk + (lane & 3);
            const int r = wid * 16 + (lane >> 2);
            uint32_t af[4];
            af[0] = f2tf32(sQ[r * 68 + kb]);
            af[1] = f2tf32(sQ[(r + 8) * 68 + kb]);
            af[2] = f2tf32(sQ[r * 68 + kb + 4]);
            af[3] = f2tf32(sQ[(r + 8) * 68 + kb + 4]);
            #pragma unroll
            for (int in = 0; in < 16; ++in) {
                int nn = in * 8 + (lane >> 2);
                uint32_t b0 = f2tf32(sK[nn * 68 + kb]);
                uint32_t b1 = f2tf32(sK[nn * 68 + kb + 4]);
                mma_tf32(sacc[in], af, b0, b1);
            }
        }

        // ---- online softmax (ADDITIVE +1.0 mask for col > row) ----
        float scale0 = 0.f, scale1 = 0.f;
        #pragma unroll
        for (int hh = 0; hh < 2; ++hh) {
            const int rw = rw0 + hh * 8;
            float cm = -1e30f;
            #pragma unroll
            for (int in = 0; in < 16; ++in) {
                int col = c * 128 + in * 8 + 2 * (lane & 3);
                float v0 = sacc[in][2 * hh]     * 0.125f + ((col     > rw) ? 1.f : 0.f);
                float v1 = sacc[in][2 * hh + 1] * 0.125f + ((col + 1 > rw) ? 1.f : 0.f);
                sacc[in][2 * hh] = v0; sacc[in][2 * hh + 1] = v1;
                cm = fmaxf(cm, fmaxf(v0, v1));
            }
            cm = fmaxf(cm, __shfl_xor_sync(0xffffffffu, cm, 1));
            cm = fmaxf(cm, __shfl_xor_sync(0xffffffffu, cm, 2));
            float mn = fmaxf(m_[hh], cm);
            float sc = __expf(m_[hh] - mn);
            float rs = 0.f;
            const int rloc = wid * 16 + (lane >> 2) + hh * 8;
            #pragma unroll
            for (int in = 0; in < 16; ++in) {
                float p0 = __expf(sacc[in][2 * hh] - mn);
                float p1 = __expf(sacc[in][2 * hh + 1] - mn);
                rs += p0 + p1;
                *(float2*)&sP[rloc * 132 + in * 8 + 2 * (lane & 3)] = make_float2(p0, p1);
            }
            rs += __shfl_xor_sync(0xffffffffu, rs, 1);
            rs += __shfl_xor_sync(0xffffffffu, rs, 2);
            l_[hh] = l_[hh] * sc + rs;
            m_[hh] = mn;
            if (hh == 0) scale0 = sc; else scale1 = sc;
        }
        #pragma unroll
        for (int in = 0; in < 8; ++in) {
            oacc[in][0] *= scale0; oacc[in][1] *= scale0;
            oacc[in][2] *= scale1; oacc[in][3] *= scale1;
        }
        __syncwarp();   // sP rows are warp-private; warp-level visibility suffices

        // ---- O += P V ----
        #pragma unroll
        for (int kk = 0; kk < 128; kk += 8) {
            const int kb = kk + (lane & 3);
            const int r = wid * 16 + (lane >> 2);
            uint32_t af[4];
            af[0] = f2tf32(sP[r * 132 + kb]);
            af[1] = f2tf32(sP[(r + 8) * 132 + kb]);
            af[2] = f2tf32(sP[r * 132 + kb + 4]);
            af[3] = f2tf32(sP[(r + 8) * 132 + kb + 4]);
            #pragma unroll
            for (int in = 0; in < 8; ++in) {
                int nn = in * 8 + (lane >> 2);
                uint32_t b0 = f2tf32(sV[kb * 72 + nn]);
                uint32_t b1 = f2tf32(sV[(kb + 4) * 72 + nn]);
                mma_tf32(oacc[in], af, b0, b1);
            }
        }
        __syncthreads();   // everyone done with sK/sV before next chunk's cp.async
    }

    // ---- epilogue: O /= l, write to ao[token][h*64 + d] ----
    const float inv0 = 1.f / l_[0], inv1 = 1.f / l_[1];
    const long long trow = (long long)win * W + q0 + wid * 16 + (lane >> 2);
    float* Od = ao + trow * 1024 + h * 64;
    #pragma unroll
    for (int in = 0; in < 8; ++in) {
        int cc = in * 8 + 2 * (lane & 3);
        *(float2*)&Od[cc]            = make_float2(oacc[in][0] * inv0, oacc[in][1] * inv0);
        *(float2*)&Od[8 * 1024 + cc] = make_float2(oacc[in][2] * inv1, oacc[in][3] * inv1);
    }
}

// ---------------------------------------------------------------------------
// driver
// ---------------------------------------------------------------------------
static const int PROJ_SMEM = (2 * 256 * 36 + 2 * 128 * 36) * 4;  // 110592
static const int ATTN_SMEM = 43520 * 4;                           // 174080

static void run_branch(const float* x, const float* w_in, const float* b_in,
                       const float* w_out, const float* b_out,
                       int W, float* out, float* qkv, float* ao)
{
    const int M = Bb * Ss;   // 16384
    gemm_proj<<<dim3(3072 / 128, M / 256), 256, PROJ_SMEM>>>(
        x, Dd, w_in, Dd, qkv, 3072, Dd, b_in);

    const int nwin = M / W;
    attn_fused<<<dim3(W / 128, nwin * Hh), 256, ATTN_SMEM>>>(qkv, ao, W, W / 128);

    gemm_proj<<<dim3(1024 / 128, M / 256), 256, PROJ_SMEM>>>(
        ao, Dd, w_out, Dd, out, Dd, Dd, b_out);
}

extern "C" void kernel_launch(void* const* d_in, const int* in_sizes, int n_in,
                              void* d_out, int out_size)
{
    const float* lqs    = (const float*)d_in[0];
    const float* gqs    = (const float*)d_in[1];
    const float* wl_in  = (const float*)d_in[2];
    const float* bl_in  = (const float*)d_in[3];
    const float* wl_out = (const float*)d_in[4];
    const float* bl_out = (const float*)d_in[5];
    const float* wg_in  = (const float*)d_in[6];
    const float* bg_in  = (const float*)d_in[7];
    const float* wg_out = (const float*)d_in[8];
    const float* bg_out = (const float*)d_in[9];
    float* out = (float*)d_out;

    cudaFuncSetAttribute(gemm_proj, cudaFuncAttributeMaxDynamicSharedMemorySize, PROJ_SMEM);
    cudaFuncSetAttribute(attn_fused, cudaFuncAttributeMaxDynamicSharedMemorySize, ATTN_SMEM);

    float *qkv, *ao;
    cudaGetSymbolAddress((void**)&qkv, g_qkv);
    cudaGetSymbolAddress((void**)&ao, g_ao);

    run_branch(lqs, wl_in, bl_in, wl_out, bl_out, 128, out, qkv, ao);
    run_branch(gqs, wg_in, bg_in, wg_out, bg_out, 1024,
               out + (size_t)Bb * Ss * Dd, qkv, ao);
}